// round 6
// baseline (speedup 1.0000x reference)
#include <cuda_runtime.h>

#define DI static __device__ __forceinline__
typedef unsigned long long ull;

namespace {
constexpr int B = 2, S = 512, H = 128, A = 7;
constexpr int BS = B * S;
constexpr float LOG2E = 1.4426950408889634f;
constexpr float LN2   = 0.6931471805599453f;
constexpr float TK0   = 0.7978845608028654f;          // sqrt(2/pi)
constexpr float TK1   = TK0 * 0.044715f;
constexpr float GK0   = -2.0f * LOG2E * TK0;          // sigmoid-form consts (action head)
constexpr float GK1   = GK0 * 0.044715f;
constexpr float EPS   = 1e-5f;
}

// scratch: 0 = action pre, 2 = hd_left, 4 = hd_right (1,3 unused now)
__device__ __align__(16) float g_pre[5][BS * H];
// hv transposed, channel-pair-major: g_hvT[head][q2][b*S + j] = float4(ch 4q2..4q2+3 of row j)
__device__ __align__(16) float4 g_hvT[2][H / 4][BS];
__device__ float g_logits[BS * A];

DI float ex2a(float x){ float y; asm("ex2.approx.ftz.f32 %0, %1;" : "=f"(y) : "f"(x)); return y; }
DI float rcpa(float x){ float y; asm("rcp.approx.ftz.f32 %0, %1;" : "=f"(y) : "f"(x)); return y; }
DI float lg2a(float x){ float y; asm("lg2.approx.ftz.f32 %0, %1;" : "=f"(y) : "f"(x)); return y; }
DI float rsqa(float x){ float y; asm("rsqrt.approx.ftz.f32 %0, %1;" : "=f"(y) : "f"(x)); return y; }
DI float tanha(float x){ float y; asm("tanh.approx.f32 %0, %1;" : "=f"(y) : "f"(x)); return y; }

// ---- packed f32x2 helpers (sm_103a) ----
DI ull pk2(float x, float y){ ull r; asm("mov.b64 %0, {%1, %2};" : "=l"(r) : "f"(x), "f"(y)); return r; }
DI void upk2(ull v, float& x, float& y){ asm("mov.b64 {%0, %1}, %2;" : "=f"(x), "=f"(y) : "l"(v)); }
DI ull add2(ull a, ull b){ ull r; asm("add.rn.f32x2 %0, %1, %2;" : "=l"(r) : "l"(a), "l"(b)); return r; }
DI ull mul2(ull a, ull b){ ull r; asm("mul.rn.f32x2 %0, %1, %2;" : "=l"(r) : "l"(a), "l"(b)); return r; }
DI ull fma2(ull a, ull b, ull c){ ull r; asm("fma.rn.f32x2 %0, %1, %2, %3;" : "=l"(r) : "l"(a), "l"(b), "l"(c)); return r; }

// exact-ish gelu for the (tiny) action head
DI float gelu_f(float x){
  float x2 = x * x;
  float w  = x * fmaf(GK1, x2, GK0);
  return x * rcpa(1.0f + ex2a(w));
}

DI float wredmax(float v){
  #pragma unroll
  for (int o = 16; o; o >>= 1) v = fmaxf(v, __shfl_xor_sync(0xffffffffu, v, o));
  return v;
}
DI float wredsum(float v){
  #pragma unroll
  for (int o = 16; o; o >>= 1) v += __shfl_xor_sync(0xffffffffu, v, o);
  return v;
}

// ---------------- P1: five [1024,128] @ [128,128] + bias GEMMs ----------------
// m=1,3 (hv matrices) stored transposed into g_hvT; others row-major to g_pre.
__global__ void __launch_bounds__(128) k_gemm(
    const float* __restrict__ x,
    const float* __restrict__ W0, const float* __restrict__ Bi0,
    const float* __restrict__ W1, const float* __restrict__ Bi1,
    const float* __restrict__ W2, const float* __restrict__ Bi2,
    const float* __restrict__ W3, const float* __restrict__ Bi3,
    const float* __restrict__ W4, const float* __restrict__ Bi4)
{
  __shared__ float xs[16][H];
  int m = blockIdx.y;
  const float* W = W0; const float* bias = Bi0;
  if      (m == 1){ W = W1; bias = Bi1; }
  else if (m == 2){ W = W2; bias = Bi2; }
  else if (m == 3){ W = W3; bias = Bi3; }
  else if (m == 4){ W = W4; bias = Bi4; }

  int r0 = blockIdx.x * 16;
  int t  = threadIdx.x;
  #pragma unroll
  for (int r = 0; r < 16; ++r) xs[r][t] = x[(r0 + r) * H + t];
  __syncthreads();

  int rt = (t >> 5) * 4;
  int c0 = (t & 31) * 4;
  float4 bv = *(const float4*)&bias[c0];
  float acc[4][4];
  #pragma unroll
  for (int i = 0; i < 4; ++i){ acc[i][0]=bv.x; acc[i][1]=bv.y; acc[i][2]=bv.z; acc[i][3]=bv.w; }

  #pragma unroll 4
  for (int h = 0; h < H; ++h) {
    float4 w4 = *(const float4*)&W[h * H + c0];
    float xv[4];
    #pragma unroll
    for (int i = 0; i < 4; ++i) xv[i] = xs[rt + i][h];
    #pragma unroll
    for (int i = 0; i < 4; ++i){
      acc[i][0] = fmaf(xv[i], w4.x, acc[i][0]);
      acc[i][1] = fmaf(xv[i], w4.y, acc[i][1]);
      acc[i][2] = fmaf(xv[i], w4.z, acc[i][2]);
      acc[i][3] = fmaf(xv[i], w4.w, acc[i][3]);
    }
  }
  if (m == 1 || m == 3) {
    int hh = (m == 1) ? 0 : 1;
    int q2 = t & 31;
    #pragma unroll
    for (int i = 0; i < 4; ++i){
      float4 o; o.x=acc[i][0]; o.y=acc[i][1]; o.z=acc[i][2]; o.w=acc[i][3];
      g_hvT[hh][q2][r0 + rt + i] = o;
    }
  } else {
    float* out = g_pre[m];
    #pragma unroll
    for (int i = 0; i < 4; ++i){
      float4 o; o.x=acc[i][0]; o.y=acc[i][1]; o.z=acc[i][2]; o.w=acc[i][3];
      *(float4*)&out[(r0 + rt + i) * H + c0] = o;
    }
  }
}

// ---------------- P2: action head rows: GeLU -> LN -> @aw2 + ab2 ----------------
__global__ void __launch_bounds__(128) k_action(
    const float* __restrict__ lng, const float* __restrict__ lnb,
    const float* __restrict__ aw2, const float* __restrict__ ab2)
{
  int row = blockIdx.x;
  int h   = threadIdx.x;
  float y = gelu_f(g_pre[0][row * H + h]);

  __shared__ float red1[4], red2[4], ys[H];
  float s1 = wredsum(y);
  float s2 = wredsum(y * y);
  int wid = h >> 5;
  if ((h & 31) == 0){ red1[wid] = s1; red2[wid] = s2; }
  __syncthreads();
  float t1 = red1[0] + red1[1] + red1[2] + red1[3];
  float t2 = red2[0] + red2[1] + red2[2] + red2[3];
  float mean = t1 * (1.0f / H);
  float var  = fmaf(-mean, mean, t2 * (1.0f / H));
  float rstd = rsqa(var + EPS);
  ys[h] = fmaf((y - mean) * rstd, lng[h], lnb[h]);
  __syncthreads();
  if (h < A){
    float acc = ab2[h];
    #pragma unroll 8
    for (int k = 0; k < H; ++k) acc = fmaf(ys[k], aw2[k * A + h], acc);
    g_logits[row * A + h] = acc;
  }
}

// ---------------- P3: action log_softmax over dim 1 (sequence) ----------------
__global__ void __launch_bounds__(512) k_actsm(float* __restrict__ out)
{
  int b = blockIdx.x / A, a = blockIdx.x % A;
  int s = threadIdx.x;
  float v = g_logits[(b * S + s) * A + a];

  __shared__ float red[16];
  __shared__ float bmax_s, bsum_s;
  int wid = s >> 5, lane = s & 31;

  float m = wredmax(v);
  if (lane == 0) red[wid] = m;
  __syncthreads();
  if (s < 32){
    float tt = (s < 16) ? red[s] : -3.4e38f;
    tt = wredmax(tt);
    if (s == 0) bmax_s = tt;
  }
  __syncthreads();
  float bmax = bmax_s;
  float e = ex2a((v - bmax) * LOG2E);
  float sm = wredsum(e);
  __syncthreads();
  if (lane == 0) red[wid] = sm;
  __syncthreads();
  if (s < 32){
    float tt = (s < 16) ? red[s] : 0.0f;
    tt = wredsum(tt);
    if (s == 0) bsum_s = tt;
  }
  __syncthreads();
  out[(b * S + s) * A + a] = v - bmax - lg2a(bsum_s) * LN2;
}

// ---------------- P4: pointer heads (f32x2 + HW tanh, transposed hv LDG) -----
// grid (S/4, B, 2), block 256 = 2 j-half groups x 4 warps; warp = one i-row.
// hv read straight from gmem (transposed, coalesced LDG.128); no staging at all.
__global__ void __launch_bounds__(256, 4) k_ptr(
    const float* __restrict__ lg, const float* __restrict__ lb,
    const float* __restrict__ lpw, const float* __restrict__ lpb,
    const float* __restrict__ rg, const float* __restrict__ rb,
    const float* __restrict__ rpw, const float* __restrict__ rpb,
    float* __restrict__ out)
{
  int head = blockIdx.z, b = blockIdx.y;
  int i0 = blockIdx.x * 4;
  const float* gv = head ? rg  : lg;
  const float* bv = head ? rb  : lb;
  const float* pw = head ? rpw : lpw;
  const float* pb = head ? rpb : lpb;
  const float* hd = g_pre[2 + 2 * head] + b * S * H;   // indexed by i

  __shared__ __align__(16) float hds[4][H];
  __shared__ __align__(16) float wgh[H];
  __shared__ float redc[4][2];
  __shared__ float cc2[2];
  __shared__ float gmaxs[2][4], gsums[2][4];

  int tid  = threadIdx.x;
  int wid  = tid >> 5, lane = tid & 31;
  int g    = tid >> 7;        // j-half group (0/1)
  int ir   = wid & 3;         // i-row within CTA

  // folded weights: wgh = g*pw ; c1 = sum(g*pw) ; c2 = sum(b*pw) + pb
  if (tid < 128) {
    float p  = pw[tid];
    float wg = gv[tid] * p;
    float tb = bv[tid] * p;
    wgh[tid] = wg;
    float r1 = wredsum(wg), r2 = wredsum(tb);
    if (lane == 0){ redc[wid][0] = r1; redc[wid][1] = r2; }
  }
  for (int idx = tid; idx < 4 * H; idx += 256)
    hds[idx >> 7][idx & (H - 1)] = hd[(i0 + (idx >> 7)) * H + (idx & (H - 1))];
  __syncthreads();
  if (tid == 0){
    cc2[0] = redc[0][0] + redc[1][0] + redc[2][0] + redc[3][0];
    cc2[1] = redc[0][1] + redc[1][1] + redc[2][1] + redc[3][1] + pb[0];
  }
  __syncthreads();
  float c1 = cc2[0], c2 = cc2[1];

  const ull K0p = pk2(TK0, TK0);
  const ull K1p = pk2(TK1, TK1);
  const ull HLp = pk2(0.5f, 0.5f);

  float sc[8];

  for (int tile = 0; tile < 8; ++tile) {
    int jb = (g * 8 + tile) * 32;
    // lane's hv row pointer: plane stride BS float4s between q2 steps
    const ulonglong2* ap = (const ulonglong2*)&g_hvT[head][0][b * S + jb + lane];
    const ulonglong2* dr = (const ulonglong2*)&hds[ir][0];
    const ulonglong2* wr = (const ulonglong2*)&wgh[0];

    ull s1 = 0, s2 = 0, s3 = 0;
    #pragma unroll 4
    for (int q2 = 0; q2 < 32; ++q2) {
      ulonglong2 a2 = ap[q2 * BS];
      ulonglong2 d2 = dr[q2];
      ulonglong2 w2 = wr[q2];
      #pragma unroll
      for (int half = 0; half < 2; ++half) {
        ull a = half ? a2.y : a2.x;
        ull d = half ? d2.y : d2.x;
        ull w = half ? w2.y : w2.x;
        ull x  = add2(a, d);
        ull x2 = mul2(x, x);
        ull p  = fma2(K1p, x2, K0p);
        ull u  = mul2(x, p);
        float u0f, u1f; upk2(u, u0f, u1f);
        ull t  = pk2(tanha(u0f), tanha(u1f));
        ull xh = mul2(x, HLp);
        ull y  = fma2(xh, t, xh);
        s1 = add2(s1, y);
        s2 = fma2(y, y, s2);
        s3 = fma2(y, w, s3);
      }
    }
    float a0,a1,b0,b1,d0,d1;
    upk2(s1, a0, a1); upk2(s2, b0, b1); upk2(s3, d0, d1);
    float t1 = a0 + a1, t2 = b0 + b1, t3 = d0 + d1;
    float mean = t1 * (1.0f / H);
    float var  = fmaf(-mean, mean, t2 * (1.0f / H));
    float rstd = rsqa(var + EPS);
    sc[tile] = fmaf(rstd, fmaf(-mean, c1, t3), c2);
  }

  // log_softmax over j: combine the two j-half groups per i-row
  float lmax = sc[0];
  #pragma unroll
  for (int k = 1; k < 8; ++k) lmax = fmaxf(lmax, sc[k]);
  lmax = wredmax(lmax);
  if (lane == 0) gmaxs[g][ir] = lmax;
  __syncthreads();
  float m = fmaxf(gmaxs[0][ir], gmaxs[1][ir]);
  float lsum = 0.f;
  #pragma unroll
  for (int k = 0; k < 8; ++k) lsum += ex2a((sc[k] - m) * LOG2E);
  lsum = wredsum(lsum);
  if (lane == 0) gsums[g][ir] = lsum;
  __syncthreads();
  float lse = lg2a(gsums[0][ir] + gsums[1][ir]) * LN2;

  float* orow = out + B * S * A + head * (B * S * S) + (b * S + i0 + ir) * S + g * 256;
  #pragma unroll
  for (int k = 0; k < 8; ++k) orow[k * 32 + lane] = sc[k] - m - lse;
}

extern "C" void kernel_launch(void* const* d_in, const int* in_sizes, int n_in,
                              void* d_out, int out_size)
{
  (void)in_sizes; (void)n_in; (void)out_size;
  const float* hiddens = (const float*)d_in[0];
  const float* aw1     = (const float*)d_in[1];
  const float* ab1     = (const float*)d_in[2];
  const float* a_ln_g  = (const float*)d_in[3];
  const float* a_ln_b  = (const float*)d_in[4];
  const float* aw2     = (const float*)d_in[5];
  const float* ab2     = (const float*)d_in[6];
  const float* lhid_w  = (const float*)d_in[7];
  const float* lhid_b  = (const float*)d_in[8];
  const float* lhead_w = (const float*)d_in[9];
  const float* lhead_b = (const float*)d_in[10];
  const float* l_ln_g  = (const float*)d_in[11];
  const float* l_ln_b  = (const float*)d_in[12];
  const float* l_proj_w= (const float*)d_in[13];
  const float* l_proj_b= (const float*)d_in[14];
  const float* rhid_w  = (const float*)d_in[15];
  const float* rhid_b  = (const float*)d_in[16];
  const float* rhead_w = (const float*)d_in[17];
  const float* rhead_b = (const float*)d_in[18];
  const float* r_ln_g  = (const float*)d_in[19];
  const float* r_ln_b  = (const float*)d_in[20];
  const float* r_proj_w= (const float*)d_in[21];
  const float* r_proj_b= (const float*)d_in[22];
  float* out = (float*)d_out;

  k_gemm<<<dim3(BS / 16, 5), 128>>>(hiddens,
      aw1, ab1, lhid_w, lhid_b, lhead_w, lhead_b, rhid_w, rhid_b, rhead_w, rhead_b);
  k_action<<<BS, 128>>>(a_ln_g, a_ln_b, aw2, ab2);
  k_actsm<<<B * A, 512>>>(out);
  k_ptr<<<dim3(S / 4, B, 2), 256>>>(l_ln_g, l_ln_b, l_proj_w, l_proj_b,
                                    r_ln_g, r_ln_b, r_proj_w, r_proj_b, out);
}

// round 7
// speedup vs baseline: 1.1081x; 1.1081x over previous
#include <cuda_runtime.h>

#define DI static __device__ __forceinline__
typedef unsigned long long ull;

namespace {
constexpr int B = 2, S = 512, H = 128, A = 7;
constexpr int BS = B * S;
constexpr float LOG2E = 1.4426950408889634f;
constexpr float LN2   = 0.6931471805599453f;
constexpr float TK0   = 0.7978845608028654f;          // sqrt(2/pi)
constexpr float TK1   = TK0 * 0.044715f;
constexpr float GK0   = -2.0f * LOG2E * TK0;          // sigmoid-form consts (action head)
constexpr float GK1   = GK0 * 0.044715f;
constexpr float EPS   = 1e-5f;
}

// scratch: 2 = hd_left, 4 = hd_right (0,1,3 unused)
__device__ __align__(16) float g_pre[5][BS * H];
// hv transposed, channel-pair-major: g_hvT[head][q2][b*S + j] = float4(ch 4q2..4q2+3 of row j)
__device__ __align__(16) float4 g_hvT[2][H / 4][BS];
__device__ float g_logits[BS * A];

DI float ex2a(float x){ float y; asm("ex2.approx.ftz.f32 %0, %1;" : "=f"(y) : "f"(x)); return y; }
DI float rcpa(float x){ float y; asm("rcp.approx.ftz.f32 %0, %1;" : "=f"(y) : "f"(x)); return y; }
DI float lg2a(float x){ float y; asm("lg2.approx.ftz.f32 %0, %1;" : "=f"(y) : "f"(x)); return y; }
DI float rsqa(float x){ float y; asm("rsqrt.approx.ftz.f32 %0, %1;" : "=f"(y) : "f"(x)); return y; }
DI float tanha(float x){ float y; asm("tanh.approx.f32 %0, %1;" : "=f"(y) : "f"(x)); return y; }

// ---- packed f32x2 helpers (sm_103a) ----
DI ull pk2(float x, float y){ ull r; asm("mov.b64 %0, {%1, %2};" : "=l"(r) : "f"(x), "f"(y)); return r; }
DI void upk2(ull v, float& x, float& y){ asm("mov.b64 {%0, %1}, %2;" : "=f"(x), "=f"(y) : "l"(v)); }
DI ull add2(ull a, ull b){ ull r; asm("add.rn.f32x2 %0, %1, %2;" : "=l"(r) : "l"(a), "l"(b)); return r; }
DI ull mul2(ull a, ull b){ ull r; asm("mul.rn.f32x2 %0, %1, %2;" : "=l"(r) : "l"(a), "l"(b)); return r; }
DI ull fma2(ull a, ull b, ull c){ ull r; asm("fma.rn.f32x2 %0, %1, %2, %3;" : "=l"(r) : "l"(a), "l"(b), "l"(c)); return r; }

// exact-ish gelu (sigmoid form) for the action head
DI float gelu_f(float x){
  float x2 = x * x;
  float w  = x * fmaf(GK1, x2, GK0);
  return x * rcpa(1.0f + ex2a(w));
}

DI float wredmax(float v){
  #pragma unroll
  for (int o = 16; o; o >>= 1) v = fmaxf(v, __shfl_xor_sync(0xffffffffu, v, o));
  return v;
}
DI float wredsum(float v){
  #pragma unroll
  for (int o = 16; o; o >>= 1) v += __shfl_xor_sync(0xffffffffu, v, o);
  return v;
}

// ---------------- P1: five [1024,128]@[128,128]+bias GEMMs, fused epilogues --
// m=0: action head fused (GeLU->LN->proj -> g_logits), no g_pre store.
// m=1,3: hv -> transposed coalesced store to g_hvT (via smem transpose).
// m=2,4: hd -> row-major g_pre.
__global__ void __launch_bounds__(128) k_gemm(
    const float* __restrict__ x,
    const float* __restrict__ W0, const float* __restrict__ Bi0,
    const float* __restrict__ W1, const float* __restrict__ Bi1,
    const float* __restrict__ W2, const float* __restrict__ Bi2,
    const float* __restrict__ W3, const float* __restrict__ Bi3,
    const float* __restrict__ W4, const float* __restrict__ Bi4,
    const float* __restrict__ lng, const float* __restrict__ lnb,
    const float* __restrict__ aw2, const float* __restrict__ ab2)
{
  __shared__ float xs[16][H];
  __shared__ __align__(16) float4 st[16][33];
  int m = blockIdx.y;
  const float* W = W0; const float* bias = Bi0;
  if      (m == 1){ W = W1; bias = Bi1; }
  else if (m == 2){ W = W2; bias = Bi2; }
  else if (m == 3){ W = W3; bias = Bi3; }
  else if (m == 4){ W = W4; bias = Bi4; }

  int r0 = blockIdx.x * 16;
  int t  = threadIdx.x;
  #pragma unroll
  for (int r = 0; r < 16; ++r) xs[r][t] = x[(r0 + r) * H + t];
  __syncthreads();

  int rt = (t >> 5) * 4;
  int c0 = (t & 31) * 4;
  int lane = t & 31;
  float4 bv = *(const float4*)&bias[c0];
  float acc[4][4];
  #pragma unroll
  for (int i = 0; i < 4; ++i){ acc[i][0]=bv.x; acc[i][1]=bv.y; acc[i][2]=bv.z; acc[i][3]=bv.w; }

  #pragma unroll 4
  for (int h = 0; h < H; ++h) {
    float4 w4 = *(const float4*)&W[h * H + c0];
    float xv[4];
    #pragma unroll
    for (int i = 0; i < 4; ++i) xv[i] = xs[rt + i][h];
    #pragma unroll
    for (int i = 0; i < 4; ++i){
      acc[i][0] = fmaf(xv[i], w4.x, acc[i][0]);
      acc[i][1] = fmaf(xv[i], w4.y, acc[i][1]);
      acc[i][2] = fmaf(xv[i], w4.z, acc[i][2]);
      acc[i][3] = fmaf(xv[i], w4.w, acc[i][3]);
    }
  }

  if (m == 0) {
    // fused action head: GeLU -> LN -> @aw2+ab2 -> g_logits (warp owns rows rt..rt+3)
    float4 lg4 = *(const float4*)&lng[c0];
    float4 lb4 = *(const float4*)&lnb[c0];
    float wa[4][7];
    #pragma unroll
    for (int k = 0; k < 4; ++k)
      #pragma unroll
      for (int a = 0; a < 7; ++a) wa[k][a] = aw2[(c0 + k) * A + a];
    #pragma unroll
    for (int i = 0; i < 4; ++i) {
      float y0 = gelu_f(acc[i][0]), y1 = gelu_f(acc[i][1]);
      float y2 = gelu_f(acc[i][2]), y3 = gelu_f(acc[i][3]);
      float s1 = wredsum(y0 + y1 + y2 + y3);
      float s2 = wredsum(y0*y0 + y1*y1 + y2*y2 + y3*y3);
      float mean = s1 * (1.0f / H);
      float var  = fmaf(-mean, mean, s2 * (1.0f / H));
      float rstd = rsqa(var + EPS);
      float z0 = fmaf((y0 - mean) * rstd, lg4.x, lb4.x);
      float z1 = fmaf((y1 - mean) * rstd, lg4.y, lb4.y);
      float z2 = fmaf((y2 - mean) * rstd, lg4.z, lb4.z);
      float z3 = fmaf((y3 - mean) * rstd, lg4.w, lb4.w);
      float part[7];
      #pragma unroll
      for (int a = 0; a < 7; ++a) {
        float p = fmaf(z0, wa[0][a], fmaf(z1, wa[1][a], fmaf(z2, wa[2][a], z3 * wa[3][a])));
        part[a] = wredsum(p);
      }
      if (lane < 7) g_logits[(r0 + rt + i) * A + lane] = part[lane] + ab2[lane];
    }
  } else if (m == 1 || m == 3) {
    int hh = (m == 1) ? 0 : 1;
    #pragma unroll
    for (int i = 0; i < 4; ++i){
      float4 o; o.x=acc[i][0]; o.y=acc[i][1]; o.z=acc[i][2]; o.w=acc[i][3];
      st[rt + i][lane] = o;
    }
    __syncthreads();
    #pragma unroll
    for (int k = 0; k < 4; ++k) {
      int idx = t + k * 128;
      int q2 = idx >> 4, r = idx & 15;
      g_hvT[hh][q2][r0 + r] = st[r][q2];
    }
  } else {
    float* out = g_pre[m];
    #pragma unroll
    for (int i = 0; i < 4; ++i){
      float4 o; o.x=acc[i][0]; o.y=acc[i][1]; o.z=acc[i][2]; o.w=acc[i][3];
      *(float4*)&out[(r0 + rt + i) * H + c0] = o;
    }
  }
}

// ---------------- P3: action log_softmax over dim 1 (sequence) ----------------
__global__ void __launch_bounds__(512) k_actsm(float* __restrict__ out)
{
  int b = blockIdx.x / A, a = blockIdx.x % A;
  int s = threadIdx.x;
  float v = g_logits[(b * S + s) * A + a];

  __shared__ float red[16];
  __shared__ float bmax_s, bsum_s;
  int wid = s >> 5, lane = s & 31;

  float m = wredmax(v);
  if (lane == 0) red[wid] = m;
  __syncthreads();
  if (s < 32){
    float tt = (s < 16) ? red[s] : -3.4e38f;
    tt = wredmax(tt);
    if (s == 0) bmax_s = tt;
  }
  __syncthreads();
  float bmax = bmax_s;
  float e = ex2a((v - bmax) * LOG2E);
  float sm = wredsum(e);
  __syncthreads();
  if (lane == 0) red[wid] = sm;
  __syncthreads();
  if (s < 32){
    float tt = (s < 16) ? red[s] : 0.0f;
    tt = wredsum(tt);
    if (s == 0) bsum_s = tt;
  }
  __syncthreads();
  out[(b * S + s) * A + a] = v - bmax - lg2a(bsum_s) * LN2;
}

// ---------------- P4: pointer heads (f32x2 + HW tanh, transposed hv LDG) -----
// grid (S/2, B, 2) = 1024 CTAs, block 256 = 2 i-rows x 4 j-quarter groups.
// warp: ir = wid>>2, g = wid&3; 4 tiles of 32 j each. No smem staging.
__global__ void __launch_bounds__(256, 5) k_ptr(
    const float* __restrict__ lg, const float* __restrict__ lb,
    const float* __restrict__ lpw, const float* __restrict__ lpb,
    const float* __restrict__ rg, const float* __restrict__ rb,
    const float* __restrict__ rpw, const float* __restrict__ rpb,
    float* __restrict__ out)
{
  int head = blockIdx.z, b = blockIdx.y;
  int i0 = blockIdx.x * 2;
  const float* gv = head ? rg  : lg;
  const float* bv = head ? rb  : lb;
  const float* pw = head ? rpw : lpw;
  const float* pb = head ? rpb : lpb;
  const float* hd = g_pre[2 + 2 * head] + b * S * H;   // indexed by i

  __shared__ __align__(16) float hds[2][H];
  __shared__ __align__(16) float wgh[H];
  __shared__ float redc[4][2];
  __shared__ float cc2[2];
  __shared__ float gmaxs[4][2], gsums[4][2];

  int tid  = threadIdx.x;
  int wid  = tid >> 5, lane = tid & 31;
  int g    = wid & 3;         // j-quarter group (0..3)
  int ir   = wid >> 2;        // i-row within CTA (0..1)

  // folded weights: wgh = g*pw ; c1 = sum(g*pw) ; c2 = sum(b*pw) + pb
  if (tid < 128) {
    float p  = pw[tid];
    float wg = gv[tid] * p;
    float tb = bv[tid] * p;
    wgh[tid] = wg;
    float r1 = wredsum(wg), r2 = wredsum(tb);
    if (lane == 0){ redc[wid][0] = r1; redc[wid][1] = r2; }
  }
  for (int idx = tid; idx < 2 * H; idx += 256)
    hds[idx >> 7][idx & (H - 1)] = hd[(i0 + (idx >> 7)) * H + (idx & (H - 1))];
  __syncthreads();
  if (tid == 0){
    cc2[0] = redc[0][0] + redc[1][0] + redc[2][0] + redc[3][0];
    cc2[1] = redc[0][1] + redc[1][1] + redc[2][1] + redc[3][1] + pb[0];
  }
  __syncthreads();
  float c1 = cc2[0], c2 = cc2[1];

  const ull K0p = pk2(TK0, TK0);
  const ull K1p = pk2(TK1, TK1);
  const ull HLp = pk2(0.5f, 0.5f);

  float sc[4];

  #pragma unroll
  for (int tile = 0; tile < 4; ++tile) {
    int jb = (g * 4 + tile) * 32;
    const ulonglong2* ap = (const ulonglong2*)&g_hvT[head][0][b * S + jb + lane];
    const ulonglong2* dr = (const ulonglong2*)&hds[ir][0];
    const ulonglong2* wr = (const ulonglong2*)&wgh[0];

    ull s1 = 0, s2 = 0, s3 = 0;
    #pragma unroll 4
    for (int q2 = 0; q2 < 32; ++q2) {
      ulonglong2 a2 = ap[q2 * BS];
      ulonglong2 d2 = dr[q2];
      ulonglong2 w2 = wr[q2];
      #pragma unroll
      for (int half = 0; half < 2; ++half) {
        ull a = half ? a2.y : a2.x;
        ull d = half ? d2.y : d2.x;
        ull w = half ? w2.y : w2.x;
        ull x  = add2(a, d);
        ull x2 = mul2(x, x);
        ull p  = fma2(K1p, x2, K0p);
        ull u  = mul2(x, p);
        float u0f, u1f; upk2(u, u0f, u1f);
        ull tt = pk2(tanha(u0f), tanha(u1f));
        ull xh = mul2(x, HLp);
        ull y  = fma2(xh, tt, xh);
        s1 = add2(s1, y);
        s2 = fma2(y, y, s2);
        s3 = fma2(y, w, s3);
      }
    }
    float a0,a1,b0,b1,d0,d1;
    upk2(s1, a0, a1); upk2(s2, b0, b1); upk2(s3, d0, d1);
    float t1 = a0 + a1, t2 = b0 + b1, t3 = d0 + d1;
    float mean = t1 * (1.0f / H);
    float var  = fmaf(-mean, mean, t2 * (1.0f / H));
    float rstd = rsqa(var + EPS);
    sc[tile] = fmaf(rstd, fmaf(-mean, c1, t3), c2);
  }

  // log_softmax over j: combine the 4 j-quarter groups per i-row
  float lmax = fmaxf(fmaxf(sc[0], sc[1]), fmaxf(sc[2], sc[3]));
  lmax = wredmax(lmax);
  if (lane == 0) gmaxs[g][ir] = lmax;
  __syncthreads();
  float m = fmaxf(fmaxf(gmaxs[0][ir], gmaxs[1][ir]), fmaxf(gmaxs[2][ir], gmaxs[3][ir]));
  float lsum = 0.f;
  #pragma unroll
  for (int k = 0; k < 4; ++k) lsum += ex2a((sc[k] - m) * LOG2E);
  lsum = wredsum(lsum);
  if (lane == 0) gsums[g][ir] = lsum;
  __syncthreads();
  float lse = lg2a(gsums[0][ir] + gsums[1][ir] + gsums[2][ir] + gsums[3][ir]) * LN2;

  float* orow = out + B * S * A + head * (B * S * S) + (b * S + i0 + ir) * S + g * 128;
  #pragma unroll
  for (int k = 0; k < 4; ++k) orow[k * 32 + lane] = sc[k] - m - lse;
}

extern "C" void kernel_launch(void* const* d_in, const int* in_sizes, int n_in,
                              void* d_out, int out_size)
{
  (void)in_sizes; (void)n_in; (void)out_size;
  const float* hiddens = (const float*)d_in[0];
  const float* aw1     = (const float*)d_in[1];
  const float* ab1     = (const float*)d_in[2];
  const float* a_ln_g  = (const float*)d_in[3];
  const float* a_ln_b  = (const float*)d_in[4];
  const float* aw2     = (const float*)d_in[5];
  const float* ab2     = (const float*)d_in[6];
  const float* lhid_w  = (const float*)d_in[7];
  const float* lhid_b  = (const float*)d_in[8];
  const float* lhead_w = (const float*)d_in[9];
  const float* lhead_b = (const float*)d_in[10];
  const float* l_ln_g  = (const float*)d_in[11];
  const float* l_ln_b  = (const float*)d_in[12];
  const float* l_proj_w= (const float*)d_in[13];
  const float* l_proj_b= (const float*)d_in[14];
  const float* rhid_w  = (const float*)d_in[15];
  const float* rhid_b  = (const float*)d_in[16];
  const float* rhead_w = (const float*)d_in[17];
  const float* rhead_b = (const float*)d_in[18];
  const float* r_ln_g  = (const float*)d_in[19];
  const float* r_ln_b  = (const float*)d_in[20];
  const float* r_proj_w= (const float*)d_in[21];
  const float* r_proj_b= (const float*)d_in[22];
  float* out = (float*)d_out;

  k_gemm<<<dim3(BS / 16, 5), 128>>>(hiddens,
      aw1, ab1, lhid_w, lhid_b, lhead_w, lhead_b, rhid_w, rhid_b, rhead_w, rhead_b,
      a_ln_g, a_ln_b, aw2, ab2);
  k_actsm<<<B * A, 512>>>(out);
  k_ptr<<<dim3(S / 2, B, 2), 256>>>(l_ln_g, l_ln_b, l_proj_w, l_proj_b,
                                    r_ln_g, r_ln_b, r_proj_w, r_proj_b, out);
}